// round 7
// baseline (speedup 1.0000x reference)
#include <cuda_runtime.h>

// ---------------------------------------------------------------------------
// 2-layer LSTM, B=2048, T=2048, I=1, H=16.
// R6 (resubmit after infra failure): warp-per-batch with (i,g | f,o) split:
//   half0 lane j owns gate rows i[j], g[j];  half1 owns f[j], o[j].
//   half0 computes i*g, half1 computes f*c; ONE shfl_xor(16) exchanges the
//   products and BOTH halves form c_new = own + recv. h = o*tanh(c) lands on
//   half1, which publishes h via SMEM. 2 SHFL/superstep (was 4).
// Layers software-pipelined (P = layer0 s+1, Q = layer1 s), MUFU.TANH acts,
// fma.rn.f32x2 packed math, double-buffered SMEM h, 1 syncwarp/superstep.
// ---------------------------------------------------------------------------

static constexpr int B = 2048;
static constexpr int T = 2048;
static constexpr int H = 16;

static __device__ __forceinline__ unsigned long long fma2(unsigned long long a,
                                                          unsigned long long b,
                                                          unsigned long long c) {
    unsigned long long d;
    asm("fma.rn.f32x2 %0, %1, %2, %3;" : "=l"(d) : "l"(a), "l"(b), "l"(c));
    return d;
}
static __device__ __forceinline__ unsigned long long pk2(float a, float b) {
    unsigned long long r;
    asm("mov.b64 %0, {%1, %2};" : "=l"(r) : "f"(a), "f"(b));
    return r;
}
static __device__ __forceinline__ void unpk2(unsigned long long v, float& a, float& b) {
    asm("mov.b64 {%0, %1}, %2;" : "=f"(a), "=f"(b) : "l"(v));
}
static __device__ __forceinline__ float tanhA(float x) {
    float r; asm("tanh.approx.f32 %0, %1;" : "=f"(r) : "f"(x)); return r;
}
// sigmoid(x) = 0.5*tanh(0.5x)+0.5
static __device__ __forceinline__ float sigA(float x) {
    return fmaf(0.5f, tanhA(0.5f * x), 0.5f);
}

__global__ __launch_bounds__(64, 7)
void lstm2_kernel(const float* __restrict__ x,
                  const float* __restrict__ h0in,
                  const float* __restrict__ c0in,
                  const float* __restrict__ Wih0,
                  const float* __restrict__ Whh0,
                  const float* __restrict__ bih0,
                  const float* __restrict__ bhh0,
                  const float* __restrict__ Wih1,
                  const float* __restrict__ Whh1,
                  const float* __restrict__ bih1,
                  const float* __restrict__ bhh1,
                  float* __restrict__ out)
{
    // [warp][buffer][32 floats: layer0 h at 0..15, layer1 h at 16..31]
    __shared__ __align__(16) float smh[2][2][32];

    const int tid  = threadIdx.x;
    const int wid  = tid >> 5;
    const int lane = tid & 31;
    const int j    = lane & 15;
    const int half = lane >> 4;
    const int b    = blockIdx.x * 2 + wid;

    const int gA = half * 16 + j;   // i[j] (half0) or f[j] (half1)
    const int gB = gA + 32;         // g[j] (half0) or o[j] (half1)

    // ---- register-resident weights ----
    unsigned long long w0A[8], w0B[8], wiA[8], wiB[8], w1A[8], w1B[8];
    const float2* Wh0v = reinterpret_cast<const float2*>(Whh0);
    const float2* Wi1v = reinterpret_cast<const float2*>(Wih1);
    const float2* Wh1v = reinterpret_cast<const float2*>(Whh1);
#pragma unroll
    for (int p = 0; p < 8; ++p) {
        float2 a  = Wh0v[gA * 8 + p]; w0A[p] = pk2(a.x, a.y);
        float2 b2 = Wh0v[gB * 8 + p]; w0B[p] = pk2(b2.x, b2.y);
        float2 c  = Wi1v[gA * 8 + p]; wiA[p] = pk2(c.x, c.y);
        float2 d  = Wi1v[gB * 8 + p]; wiB[p] = pk2(d.x, d.y);
        float2 e  = Wh1v[gA * 8 + p]; w1A[p] = pk2(e.x, e.y);
        float2 f  = Wh1v[gB * 8 + p]; w1B[p] = pk2(f.x, f.y);
    }
    const unsigned long long bias2A0 = pk2(bih0[gA] + bhh0[gA], 0.0f);
    const unsigned long long bias2B0 = pk2(bih0[gB] + bhh0[gB], 0.0f);
    const unsigned long long bias2A1 = pk2(bih1[gA] + bhh1[gA], 0.0f);
    const unsigned long long bias2B1 = pk2(bih1[gB] + bhh1[gB], 0.0f);
    const float wxA = Wih0[gA];     // I == 1
    const float wxB = Wih0[gB];
    const unsigned long long ONE2 = pk2(1.0f, 1.0f);

    // chain-B activation: half0 -> tanh (g), half1 -> sigmoid (o)
    const float kB = half ? 0.5f : 1.0f;
    const float cB = half ? 0.5f : 0.0f;

    // ---- state: c kept identically on both halves; h authoritative on half1
    float c0v = c0in[b * H + j];
    float c1v = c0in[B * H + b * H + j];
    float h0v = h0in[b * H + j];
    float h1v = h0in[B * H + b * H + j];

    float* bufA = smh[wid][0];
    float* bufB = smh[wid][1];
    if (half) { bufA[j] = h0v; bufA[16 + j] = h1v; }
    __syncwarp();

    const float* xrow = x + (size_t)b * T;
    float*       outp = out + (size_t)b * T * H + j;

    // ======================= prologue: layer0 step 0 =======================
    {
        const float xv0 = __ldg(xrow);
        const ulonglong2* hp = reinterpret_cast<const ulonglong2*>(bufA);
        ulonglong2 u0 = hp[0], u1 = hp[1], u2 = hp[2], u3 = hp[3];
        unsigned long long aA = bias2A0, aB = bias2B0, aA2 = 0ull, aB2 = 0ull;
        aA  = fma2(w0A[0], u0.x, aA);   aB  = fma2(w0B[0], u0.x, aB);
        aA  = fma2(w0A[1], u0.y, aA);   aB  = fma2(w0B[1], u0.y, aB);
        aA  = fma2(w0A[2], u1.x, aA);   aB  = fma2(w0B[2], u1.x, aB);
        aA  = fma2(w0A[3], u1.y, aA);   aB  = fma2(w0B[3], u1.y, aB);
        aA2 = fma2(w0A[4], u2.x, aA2);  aB2 = fma2(w0B[4], u2.x, aB2);
        aA2 = fma2(w0A[5], u2.y, aA2);  aB2 = fma2(w0B[5], u2.y, aB2);
        aA2 = fma2(w0A[6], u3.x, aA2);  aB2 = fma2(w0B[6], u3.x, aB2);
        aA2 = fma2(w0A[7], u3.y, aA2);  aB2 = fma2(w0B[7], u3.y, aB2);
        aA  = fma2(aA2, ONE2, aA);      aB  = fma2(aB2, ONE2, aB);
        float aL, aH, bL, bH;
        unpk2(aA, aL, aH); unpk2(aB, bL, bH);
        const float gAraw = fmaf(xv0, wxA, aL + aH);
        const float gBraw = fmaf(xv0, wxB, bL + bH);
        const float sA = sigA(gAraw);                        // i | f
        const float sB = fmaf(kB, tanhA(kB * gBraw), cB);    // g | o
        const float pm = sA * (half ? c0v : sB);             // f*c | i*g
        const float pe = __shfl_xor_sync(0xffffffffu, pm, 16);
        c0v = pm + pe;
        h0v = sB * tanhA(c0v);          // valid on half1 (o * tanh(c))
        __syncwarp();
        if (half) bufA[j] = h0v;        // h0(0) -> bufA
        __syncwarp();
    }

    float xv = __ldg(xrow + 1);   // x for layer0 step 1 (superstep 0)

    // superstep s: reads RB = h0(s), h1(s-1); writes WB = h0(s+1), h1(s).
#define SUPERSTEP(RB, WB, SIDX)                                                \
    {                                                                          \
        const ulonglong2* hp0 = reinterpret_cast<const ulonglong2*>(RB);       \
        const ulonglong2* hp1 = reinterpret_cast<const ulonglong2*>((RB) + 16);\
        ulonglong2 u0 = hp0[0], u1 = hp0[1], u2 = hp0[2], u3 = hp0[3];         \
        ulonglong2 v0 = hp1[0], v1 = hp1[1], v2 = hp1[2], v3 = hp1[3];         \
        const float xnext = __ldg(xrow + min((SIDX) + 2, T - 1));              \
        unsigned long long pA = bias2A0, pB = bias2B0, pA2 = 0ull, pB2 = 0ull; \
        pA  = fma2(w0A[0], u0.x, pA);   pB  = fma2(w0B[0], u0.x, pB);          \
        pA  = fma2(w0A[1], u0.y, pA);   pB  = fma2(w0B[1], u0.y, pB);          \
        pA  = fma2(w0A[2], u1.x, pA);   pB  = fma2(w0B[2], u1.x, pB);          \
        pA  = fma2(w0A[3], u1.y, pA);   pB  = fma2(w0B[3], u1.y, pB);          \
        pA2 = fma2(w0A[4], u2.x, pA2);  pB2 = fma2(w0B[4], u2.x, pB2);         \
        pA2 = fma2(w0A[5], u2.y, pA2);  pB2 = fma2(w0B[5], u2.y, pB2);         \
        pA2 = fma2(w0A[6], u3.x, pA2);  pB2 = fma2(w0B[6], u3.x, pB2);         \
        pA2 = fma2(w0A[7], u3.y, pA2);  pB2 = fma2(w0B[7], u3.y, pB2);         \
        unsigned long long qUA = bias2A1, qUB = bias2B1;                       \
        unsigned long long qUA2 = 0ull,  qUB2 = 0ull;                          \
        unsigned long long qVA = 0ull,   qVB = 0ull;                           \
        unsigned long long qVA2 = 0ull,  qVB2 = 0ull;                          \
        qUA  = fma2(wiA[0], u0.x, qUA);   qUB  = fma2(wiB[0], u0.x, qUB);      \
        qVA  = fma2(w1A[0], v0.x, qVA);   qVB  = fma2(w1B[0], v0.x, qVB);      \
        qUA  = fma2(wiA[1], u0.y, qUA);   qUB  = fma2(wiB[1], u0.y, qUB);      \
        qVA  = fma2(w1A[1], v0.y, qVA);   qVB  = fma2(w1B[1], v0.y, qVB);      \
        qUA  = fma2(wiA[2], u1.x, qUA);   qUB  = fma2(wiB[2], u1.x, qUB);      \
        qVA  = fma2(w1A[2], v1.x, qVA);   qVB  = fma2(w1B[2], v1.x, qVB);      \
        qUA  = fma2(wiA[3], u1.y, qUA);   qUB  = fma2(wiB[3], u1.y, qUB);      \
        qVA  = fma2(w1A[3], v1.y, qVA);   qVB  = fma2(w1B[3], v1.y, qVB);      \
        qUA2 = fma2(wiA[4], u2.x, qUA2);  qUB2 = fma2(wiB[4], u2.x, qUB2);     \
        qVA2 = fma2(w1A[4], v2.x, qVA2);  qVB2 = fma2(w1B[4], v2.x, qVB2);     \
        qUA2 = fma2(wiA[5], u2.y, qUA2);  qUB2 = fma2(wiB[5], u2.y, qUB2);     \
        qVA2 = fma2(w1A[5], v2.y, qVA2);  qVB2 = fma2(w1B[5], v2.y, qVB2);     \
        qUA2 = fma2(wiA[6], u3.x, qUA2);  qUB2 = fma2(wiB[6], u3.x, qUB2);     \
        qVA2 = fma2(w1A[6], v3.x, qVA2);  qVB2 = fma2(w1B[6], v3.x, qVB2);     \
        qUA2 = fma2(wiA[7], u3.y, qUA2);  qUB2 = fma2(wiB[7], u3.y, qUB2);     \
        qVA2 = fma2(w1A[7], v3.y, qVA2);  qVB2 = fma2(w1B[7], v3.y, qVB2);     \
        const unsigned long long paA = fma2(pA2, ONE2, pA);                    \
        const unsigned long long paB = fma2(pB2, ONE2, pB);                    \
        const unsigned long long qsA1 = fma2(qUA2, ONE2, qUA);                 \
        const unsigned long long qsB1 = fma2(qUB2, ONE2, qUB);                 \
        const unsigned long long qsA2 = fma2(qVA2, ONE2, qVA);                 \
        const unsigned long long qsB2 = fma2(qVB2, ONE2, qVB);                 \
        const unsigned long long qaA = fma2(qsA2, ONE2, qsA1);                 \
        const unsigned long long qaB = fma2(qsB2, ONE2, qsB1);                 \
        float paL, paH, pbL, pbH, qaL, qaH, qbL, qbH;                          \
        unpk2(paA, paL, paH); unpk2(paB, pbL, pbH);                            \
        unpk2(qaA, qaL, qaH); unpk2(qaB, qbL, qbH);                            \
        const float pAraw = fmaf(xv, wxA, paL + paH);                          \
        const float pBraw = fmaf(xv, wxB, pbL + pbH);                          \
        const float qAraw = qaL + qaH;                                         \
        const float qBraw = qbL + qbH;                                         \
        const float psA = sigA(pAraw);                                         \
        const float qsA = sigA(qAraw);                                         \
        const float psB = fmaf(kB, tanhA(kB * pBraw), cB);                     \
        const float qsB = fmaf(kB, tanhA(kB * qBraw), cB);                     \
        const float pm = psA * (half ? c0v : psB);                             \
        const float qm = qsA * (half ? c1v : qsB);                             \
        const float pe = __shfl_xor_sync(0xffffffffu, pm, 16);                 \
        const float qe = __shfl_xor_sync(0xffffffffu, qm, 16);                 \
        c0v = pm + pe;                                                         \
        c1v = qm + qe;                                                         \
        h0v = psB * tanhA(c0v);                                                \
        h1v = qsB * tanhA(c1v);                                                \
        if (half) {                                                            \
            (WB)[j]      = h0v;                                                \
            (WB)[16 + j] = h1v;                                                \
            *outp = h1v;                                                       \
        }                                                                      \
        outp += H;                                                             \
        xv = xnext;                                                            \
        __syncwarp();                                                          \
    }

    // supersteps s = 0 .. T-2 (2047 total): 1023 pairs + 1 final
    for (int s = 0; s < T - 3; s += 2) {
        SUPERSTEP(bufA, bufB, s)
        SUPERSTEP(bufB, bufA, s + 1)
    }
    SUPERSTEP(bufA, bufB, T - 2)

    // =================== tail: layer1 step T-1 (reads bufB) ================
    {
        const ulonglong2* hp0 = reinterpret_cast<const ulonglong2*>(bufB);
        const ulonglong2* hp1 = reinterpret_cast<const ulonglong2*>(bufB + 16);
        ulonglong2 u0 = hp0[0], u1 = hp0[1], u2 = hp0[2], u3 = hp0[3];
        ulonglong2 v0 = hp1[0], v1 = hp1[1], v2 = hp1[2], v3 = hp1[3];
        unsigned long long qUA = bias2A1, qUB = bias2B1;
        unsigned long long qVA = 0ull,   qVB = 0ull;
        qUA = fma2(wiA[0], u0.x, qUA);  qUB = fma2(wiB[0], u0.x, qUB);
        qVA = fma2(w1A[0], v0.x, qVA);  qVB = fma2(w1B[0], v0.x, qVB);
        qUA = fma2(wiA[1], u0.y, qUA);  qUB = fma2(wiB[1], u0.y, qUB);
        qVA = fma2(w1A[1], v0.y, qVA);  qVB = fma2(w1B[1], v0.y, qVB);
        qUA = fma2(wiA[2], u1.x, qUA);  qUB = fma2(wiB[2], u1.x, qUB);
        qVA = fma2(w1A[2], v1.x, qVA);  qVB = fma2(w1B[2], v1.x, qVB);
        qUA = fma2(wiA[3], u1.y, qUA);  qUB = fma2(wiB[3], u1.y, qUB);
        qVA = fma2(w1A[3], v1.y, qVA);  qVB = fma2(w1B[3], v1.y, qVB);
        qUA = fma2(wiA[4], u2.x, qUA);  qUB = fma2(wiB[4], u2.x, qUB);
        qVA = fma2(w1A[4], v2.x, qVA);  qVB = fma2(w1B[4], v2.x, qVB);
        qUA = fma2(wiA[5], u2.y, qUA);  qUB = fma2(wiB[5], u2.y, qUB);
        qVA = fma2(w1A[5], v2.y, qVA);  qVB = fma2(w1B[5], v2.y, qVB);
        qUA = fma2(wiA[6], u3.x, qUA);  qUB = fma2(wiB[6], u3.x, qUB);
        qVA = fma2(w1A[6], v3.x, qVA);  qVB = fma2(w1B[6], v3.x, qVB);
        qUA = fma2(wiA[7], u3.y, qUA);  qUB = fma2(wiB[7], u3.y, qUB);
        qVA = fma2(w1A[7], v3.y, qVA);  qVB = fma2(w1B[7], v3.y, qVB);
        const unsigned long long qaA = fma2(qVA, ONE2, qUA);
        const unsigned long long qaB = fma2(qVB, ONE2, qUB);
        float qaL, qaH, qbL, qbH;
        unpk2(qaA, qaL, qaH); unpk2(qaB, qbL, qbH);
        const float qAraw = qaL + qaH;
        const float qBraw = qbL + qbH;
        const float qsA = sigA(qAraw);
        const float qsB = fmaf(kB, tanhA(kB * qBraw), cB);
        const float qm = qsA * (half ? c1v : qsB);
        const float qe = __shfl_xor_sync(0xffffffffu, qm, 16);
        c1v = qm + qe;
        h1v = qsB * tanhA(c1v);
        if (half) *outp = h1v;
    }

    // final states: hN [2,B,H] then cN [2,B,H] appended after out1 [B,T,H]
    if (half) {
        float* hN = out + (size_t)B * T * H;
        float* cN = hN + 2 * B * H;
        hN[b * H + j]         = h0v;
        hN[B * H + b * H + j] = h1v;
        cN[b * H + j]         = c0v;
        cN[B * H + b * H + j] = c1v;
    }
}

extern "C" void kernel_launch(void* const* d_in, const int* in_sizes, int n_in,
                              void* d_out, int out_size) {
    const float* x    = (const float*)d_in[0];
    const float* h0   = (const float*)d_in[1];
    const float* c0   = (const float*)d_in[2];
    const float* Wih0 = (const float*)d_in[3];
    const float* Whh0 = (const float*)d_in[4];
    const float* bih0 = (const float*)d_in[5];
    const float* bhh0 = (const float*)d_in[6];
    const float* Wih1 = (const float*)d_in[7];
    const float* Whh1 = (const float*)d_in[8];
    const float* bih1 = (const float*)d_in[9];
    const float* bhh1 = (const float*)d_in[10];
    float* out = (float*)d_out;

    lstm2_kernel<<<B / 2, 64>>>(x, h0, c0, Wih0, Whh0, bih0, bhh0,
                                Wih1, Whh1, bih1, bhh1, out);
}

// round 8
// speedup vs baseline: 1.7986x; 1.7986x over previous
#include <cuda_runtime.h>

// ---------------------------------------------------------------------------
// 2-layer LSTM, B=2048, T=2048, I=1, H=16.
// R8 = R4 chassis (warp-per-batch, layers software-pipelined, MUFU.TANH,
// fma.rn.f32x2, double-buffered SMEM h) with:
//   - branch-free epilogue: both halves keep bit-identical c/h via SELs
//     (f_eff/o_eff), single unconditional STS publish, predicated STG.
//   - sigmoid rows (i,f,o) of all weight matrices prescaled by 0.5 so
//     sigmoid(x) = fmaf(0.5, tanh(raw), 0.5) with no input multiply.
//   - accumulator structure identical to R4 (8 live u64 accums).
// ---------------------------------------------------------------------------

static constexpr int B = 2048;
static constexpr int T = 2048;
static constexpr int H = 16;

static __device__ __forceinline__ unsigned long long fma2(unsigned long long a,
                                                          unsigned long long b,
                                                          unsigned long long c) {
    unsigned long long d;
    asm("fma.rn.f32x2 %0, %1, %2, %3;" : "=l"(d) : "l"(a), "l"(b), "l"(c));
    return d;
}
static __device__ __forceinline__ unsigned long long pk2(float a, float b) {
    unsigned long long r;
    asm("mov.b64 %0, {%1, %2};" : "=l"(r) : "f"(a), "f"(b));
    return r;
}
static __device__ __forceinline__ void unpk2(unsigned long long v, float& a, float& b) {
    asm("mov.b64 {%0, %1}, %2;" : "=f"(a), "=f"(b) : "l"(v));
}
static __device__ __forceinline__ float tanhA(float x) {
    float r; asm("tanh.approx.f32 %0, %1;" : "=f"(r) : "f"(x)); return r;
}

__global__ __launch_bounds__(64, 7)
void lstm2_kernel(const float* __restrict__ x,
                  const float* __restrict__ h0in,
                  const float* __restrict__ c0in,
                  const float* __restrict__ Wih0,
                  const float* __restrict__ Whh0,
                  const float* __restrict__ bih0,
                  const float* __restrict__ bhh0,
                  const float* __restrict__ Wih1,
                  const float* __restrict__ Whh1,
                  const float* __restrict__ bih1,
                  const float* __restrict__ bhh1,
                  float* __restrict__ out)
{
    // [warp][buffer][32 floats: layer0 h at 0..15, layer1 h at 16..31]
    __shared__ __align__(16) float smh[2][2][32];

    const int tid  = threadIdx.x;
    const int wid  = tid >> 5;
    const int lane = tid & 31;
    const int j    = lane & 15;
    const int half = lane >> 4;
    const int b    = blockIdx.x * 2 + wid;

    const int gA = half * 32 + j;   // i[j] (half0) or g[j] (half1)
    const int gB = gA + 16;         // f[j] (half0) or o[j] (half1)

    // per-row prescale: sigmoid rows (i,f,o) x0.5; tanh row (g) x1.
    const float scA = half ? 1.0f : 0.5f;   // gA: i -> 0.5, g -> 1.0
    const float scB = 0.5f;                 // gB: f or o -> always 0.5

    // ---- register-resident weights (prescaled) ----
    unsigned long long w0A[8], w0B[8], wiA[8], wiB[8], w1A[8], w1B[8];
    const float2* Wh0v = reinterpret_cast<const float2*>(Whh0);
    const float2* Wi1v = reinterpret_cast<const float2*>(Wih1);
    const float2* Wh1v = reinterpret_cast<const float2*>(Whh1);
#pragma unroll
    for (int p = 0; p < 8; ++p) {
        float2 a  = Wh0v[gA * 8 + p]; w0A[p] = pk2(a.x * scA, a.y * scA);
        float2 b2 = Wh0v[gB * 8 + p]; w0B[p] = pk2(b2.x * scB, b2.y * scB);
        float2 c  = Wi1v[gA * 8 + p]; wiA[p] = pk2(c.x * scA, c.y * scA);
        float2 d  = Wi1v[gB * 8 + p]; wiB[p] = pk2(d.x * scB, d.y * scB);
        float2 e  = Wh1v[gA * 8 + p]; w1A[p] = pk2(e.x * scA, e.y * scA);
        float2 f  = Wh1v[gB * 8 + p]; w1B[p] = pk2(f.x * scB, f.y * scB);
    }
    const unsigned long long bias2A0 = pk2((bih0[gA] + bhh0[gA]) * scA, 0.0f);
    const unsigned long long bias2B0 = pk2((bih0[gB] + bhh0[gB]) * scB, 0.0f);
    const unsigned long long bias2A1 = pk2((bih1[gA] + bhh1[gA]) * scA, 0.0f);
    const unsigned long long bias2B1 = pk2((bih1[gB] + bhh1[gB]) * scB, 0.0f);
    const float wxA = Wih0[gA] * scA;   // I == 1
    const float wxB = Wih0[gB] * scB;
    const unsigned long long ONE2 = pk2(1.0f, 1.0f);

    // chain-A activation: half0 sigmoid (0.5*t+0.5, raw prescaled), half1 tanh
    const float mA = half ? 1.0f : 0.5f;
    const float cA = half ? 0.0f : 0.5f;

    // ---- state: BOTH halves keep bit-identical c/h ----
    float c0v = c0in[b * H + j];
    float c1v = c0in[B * H + b * H + j];
    float h0v = h0in[b * H + j];
    float h1v = h0in[B * H + b * H + j];

    float* bufA = smh[wid][0];
    float* bufB = smh[wid][1];
    bufA[j + half * 16] = half ? h1v : h0v;   // both slots filled, no branch
    __syncwarp();

    const float* xrow = x + (size_t)b * T;
    float*       outp = out + (size_t)b * T * H + j;

    // ======================= prologue: layer0 step 0 =======================
    {
        const float xv0 = __ldg(xrow);
        const ulonglong2* hp = reinterpret_cast<const ulonglong2*>(bufA);
        ulonglong2 u0 = hp[0], u1 = hp[1], u2 = hp[2], u3 = hp[3];
        unsigned long long aA = bias2A0, aB = bias2B0, aA2 = 0ull, aB2 = 0ull;
        aA  = fma2(w0A[0], u0.x, aA);   aB  = fma2(w0B[0], u0.x, aB);
        aA  = fma2(w0A[1], u0.y, aA);   aB  = fma2(w0B[1], u0.y, aB);
        aA  = fma2(w0A[2], u1.x, aA);   aB  = fma2(w0B[2], u1.x, aB);
        aA  = fma2(w0A[3], u1.y, aA);   aB  = fma2(w0B[3], u1.y, aB);
        aA2 = fma2(w0A[4], u2.x, aA2);  aB2 = fma2(w0B[4], u2.x, aB2);
        aA2 = fma2(w0A[5], u2.y, aA2);  aB2 = fma2(w0B[5], u2.y, aB2);
        aA2 = fma2(w0A[6], u3.x, aA2);  aB2 = fma2(w0B[6], u3.x, aB2);
        aA2 = fma2(w0A[7], u3.y, aA2);  aB2 = fma2(w0B[7], u3.y, aB2);
        aA  = fma2(aA2, ONE2, aA);      aB  = fma2(aB2, ONE2, aB);
        float aL, aH, bL, bH;
        unpk2(aA, aL, aH); unpk2(aB, bL, bH);
        const float gAraw = fmaf(xv0, wxA, aL + aH);
        const float gBraw = fmaf(xv0, wxB, bL + bH);
        const float sA = fmaf(mA, tanhA(gAraw), cA);       // sig_i | tanh_g
        const float sB = fmaf(0.5f, tanhA(gBraw), 0.5f);   // sig_f | sig_o
        const float gg = __shfl_xor_sync(0xffffffffu, sA, 16);
        const float oo = __shfl_xor_sync(0xffffffffu, sB, 16);
        const float f_eff = half ? oo : sB;
        const float o_eff = half ? sB : oo;
        c0v = fmaf(f_eff, c0v, sA * gg);
        h0v = o_eff * tanhA(c0v);
        __syncwarp();                 // reads of bufA done before overwrite
        if (!half) bufA[j] = h0v;     // h0(0) -> bufA (h1 slot must persist)
        __syncwarp();
    }

    float xv = __ldg(xrow + 1);   // x for layer0 step 1 (superstep 0)

    // superstep s: reads RB = h0(s), h1(s-1); writes WB = h0(s+1), h1(s).
#define SUPERSTEP(RB, WB, SIDX)                                                \
    {                                                                          \
        const ulonglong2* hp0 = reinterpret_cast<const ulonglong2*>(RB);       \
        const ulonglong2* hp1 = reinterpret_cast<const ulonglong2*>((RB) + 16);\
        ulonglong2 u0 = hp0[0], u1 = hp0[1], u2 = hp0[2], u3 = hp0[3];         \
        ulonglong2 v0 = hp1[0], v1 = hp1[1], v2 = hp1[2], v3 = hp1[3];         \
        const float xnext = __ldg(xrow + min((SIDX) + 2, T - 1));              \
        unsigned long long pA = bias2A0, pB = bias2B0, pA2 = 0ull, pB2 = 0ull; \
        pA  = fma2(w0A[0], u0.x, pA);   pB  = fma2(w0B[0], u0.x, pB);          \
        pA  = fma2(w0A[1], u0.y, pA);   pB  = fma2(w0B[1], u0.y, pB);          \
        pA  = fma2(w0A[2], u1.x, pA);   pB  = fma2(w0B[2], u1.x, pB);          \
        pA  = fma2(w0A[3], u1.y, pA);   pB  = fma2(w0B[3], u1.y, pB);          \
        pA2 = fma2(w0A[4], u2.x, pA2);  pB2 = fma2(w0B[4], u2.x, pB2);         \
        pA2 = fma2(w0A[5], u2.y, pA2);  pB2 = fma2(w0B[5], u2.y, pB2);         \
        pA2 = fma2(w0A[6], u3.x, pA2);  pB2 = fma2(w0B[6], u3.x, pB2);         \
        pA2 = fma2(w0A[7], u3.y, pA2);  pB2 = fma2(w0B[7], u3.y, pB2);         \
        unsigned long long qUA = bias2A1, qUB = bias2B1;                       \
        unsigned long long qVA = 0ull,   qVB = 0ull;                           \
        qUA = fma2(wiA[0], u0.x, qUA);  qUB = fma2(wiB[0], u0.x, qUB);         \
        qVA = fma2(w1A[0], v0.x, qVA);  qVB = fma2(w1B[0], v0.x, qVB);         \
        qUA = fma2(wiA[1], u0.y, qUA);  qUB = fma2(wiB[1], u0.y, qUB);         \
        qVA = fma2(w1A[1], v0.y, qVA);  qVB = fma2(w1B[1], v0.y, qVB);         \
        qUA = fma2(wiA[2], u1.x, qUA);  qUB = fma2(wiB[2], u1.x, qUB);         \
        qVA = fma2(w1A[2], v1.x, qVA);  qVB = fma2(w1B[2], v1.x, qVB);         \
        qUA = fma2(wiA[3], u1.y, qUA);  qUB = fma2(wiB[3], u1.y, qUB);         \
        qVA = fma2(w1A[3], v1.y, qVA);  qVB = fma2(w1B[3], v1.y, qVB);         \
        qUA = fma2(wiA[4], u2.x, qUA);  qUB = fma2(wiB[4], u2.x, qUB);         \
        qVA = fma2(w1A[4], v2.x, qVA);  qVB = fma2(w1B[4], v2.x, qVB);         \
        qUA = fma2(wiA[5], u2.y, qUA);  qUB = fma2(wiB[5], u2.y, qUB);         \
        qVA = fma2(w1A[5], v2.y, qVA);  qVB = fma2(w1B[5], v2.y, qVB);         \
        qUA = fma2(wiA[6], u3.x, qUA);  qUB = fma2(wiB[6], u3.x, qUB);         \
        qVA = fma2(w1A[6], v3.x, qVA);  qVB = fma2(w1B[6], v3.x, qVB);         \
        qUA = fma2(wiA[7], u3.y, qUA);  qUB = fma2(wiB[7], u3.y, qUB);         \
        qVA = fma2(w1A[7], v3.y, qVA);  qVB = fma2(w1B[7], v3.y, qVB);         \
        const unsigned long long paA = fma2(pA2, ONE2, pA);                    \
        const unsigned long long paB = fma2(pB2, ONE2, pB);                    \
        const unsigned long long qaA = fma2(qVA, ONE2, qUA);                   \
        const unsigned long long qaB = fma2(qVB, ONE2, qUB);                   \
        float paL, paH, pbL, pbH, qaL, qaH, qbL, qbH;                          \
        unpk2(paA, paL, paH); unpk2(paB, pbL, pbH);                            \
        unpk2(qaA, qaL, qaH); unpk2(qaB, qbL, qbH);                            \
        const float pAraw = fmaf(xv, wxA, paL + paH);                          \
        const float pBraw = fmaf(xv, wxB, pbL + pbH);                          \
        const float qAraw = qaL + qaH;                                         \
        const float qBraw = qbL + qbH;                                         \
        const float psA = fmaf(mA, tanhA(pAraw), cA);                          \
        const float qsA = fmaf(mA, tanhA(qAraw), cA);                          \
        const float psB = fmaf(0.5f, tanhA(pBraw), 0.5f);                      \
        const float qsB = fmaf(0.5f, tanhA(qBraw), 0.5f);                      \
        const float pgg = __shfl_xor_sync(0xffffffffu, psA, 16);               \
        const float qgg = __shfl_xor_sync(0xffffffffu, qsA, 16);               \
        const float poo = __shfl_xor_sync(0xffffffffu, psB, 16);               \
        const float qoo = __shfl_xor_sync(0xffffffffu, qsB, 16);               \
        const float pf = half ? poo : psB;                                     \
        const float po = half ? psB : poo;                                     \
        const float qf = half ? qoo : qsB;                                     \
        const float qo = half ? qsB : qoo;                                     \
        c0v = fmaf(pf, c0v, psA * pgg);                                        \
        c1v = fmaf(qf, c1v, qsA * qgg);                                        \
        h0v = po * tanhA(c0v);                                                 \
        h1v = qo * tanhA(c1v);                                                 \
        (WB)[j + half * 16] = half ? h1v : h0v;                                \
        if (half) *outp = h1v;                                                 \
        outp += H;                                                             \
        xv = xnext;                                                            \
        __syncwarp();                                                          \
    }

    // supersteps s = 0 .. T-2 (2047 total): 1023 pairs + 1 final
    for (int s = 0; s < T - 3; s += 2) {
        SUPERSTEP(bufA, bufB, s)
        SUPERSTEP(bufB, bufA, s + 1)
    }
    SUPERSTEP(bufA, bufB, T - 2)

    // =================== tail: layer1 step T-1 (reads bufB) ================
    {
        const ulonglong2* hp0 = reinterpret_cast<const ulonglong2*>(bufB);
        const ulonglong2* hp1 = reinterpret_cast<const ulonglong2*>(bufB + 16);
        ulonglong2 u0 = hp0[0], u1 = hp0[1], u2 = hp0[2], u3 = hp0[3];
        ulonglong2 v0 = hp1[0], v1 = hp1[1], v2 = hp1[2], v3 = hp1[3];
        unsigned long long qUA = bias2A1, qUB = bias2B1;
        unsigned long long qVA = 0ull,   qVB = 0ull;
        qUA = fma2(wiA[0], u0.x, qUA);  qUB = fma2(wiB[0], u0.x, qUB);
        qVA = fma2(w1A[0], v0.x, qVA);  qVB = fma2(w1B[0], v0.x, qVB);
        qUA = fma2(wiA[1], u0.y, qUA);  qUB = fma2(wiB[1], u0.y, qUB);
        qVA = fma2(w1A[1], v0.y, qVA);  qVB = fma2(w1B[1], v0.y, qVB);
        qUA = fma2(wiA[2], u1.x, qUA);  qUB = fma2(wiB[2], u1.x, qUB);
        qVA = fma2(w1A[2], v1.x, qVA);  qVB = fma2(w1B[2], v1.x, qVB);
        qUA = fma2(wiA[3], u1.y, qUA);  qUB = fma2(wiB[3], u1.y, qUB);
        qVA = fma2(w1A[3], v1.y, qVA);  qVB = fma2(w1B[3], v1.y, qVB);
        qUA = fma2(wiA[4], u2.x, qUA);  qUB = fma2(wiB[4], u2.x, qUB);
        qVA = fma2(w1A[4], v2.x, qVA);  qVB = fma2(w1B[4], v2.x, qVB);
        qUA = fma2(wiA[5], u2.y, qUA);  qUB = fma2(wiB[5], u2.y, qUB);
        qVA = fma2(w1A[5], v2.y, qVA);  qVB = fma2(w1B[5], v2.y, qVB);
        qUA = fma2(wiA[6], u3.x, qUA);  qUB = fma2(wiB[6], u3.x, qUB);
        qVA = fma2(w1A[6], v3.x, qVA);  qVB = fma2(w1B[6], v3.x, qVB);
        qUA = fma2(wiA[7], u3.y, qUA);  qUB = fma2(wiB[7], u3.y, qUB);
        qVA = fma2(w1A[7], v3.y, qVA);  qVB = fma2(w1B[7], v3.y, qVB);
        const unsigned long long qaA = fma2(qVA, ONE2, qUA);
        const unsigned long long qaB = fma2(qVB, ONE2, qUB);
        float qaL, qaH, qbL, qbH;
        unpk2(qaA, qaL, qaH); unpk2(qaB, qbL, qbH);
        const float qAraw = qaL + qaH;
        const float qBraw = qbL + qbH;
        const float qsA = fmaf(mA, tanhA(qAraw), cA);
        const float qsB = fmaf(0.5f, tanhA(qBraw), 0.5f);
        const float qgg = __shfl_xor_sync(0xffffffffu, qsA, 16);
        const float qoo = __shfl_xor_sync(0xffffffffu, qsB, 16);
        const float qf = half ? qoo : qsB;
        const float qo = half ? qsB : qoo;
        c1v = fmaf(qf, c1v, qsA * qgg);
        h1v = qo * tanhA(c1v);
        if (half) *outp = h1v;
    }

    // final states: hN [2,B,H] then cN [2,B,H] appended after out1 [B,T,H]
    {
        float* hN = out + (size_t)B * T * H;
        float* cN = hN + 2 * B * H;
        const int off = half * (B * H) + b * H + j;
        hN[off] = half ? h1v : h0v;
        cN[off] = half ? c1v : c0v;
    }
}

extern "C" void kernel_launch(void* const* d_in, const int* in_sizes, int n_in,
                              void* d_out, int out_size) {
    const float* x    = (const float*)d_in[0];
    const float* h0   = (const float*)d_in[1];
    const float* c0   = (const float*)d_in[2];
    const float* Wih0 = (const float*)d_in[3];
    const float* Whh0 = (const float*)d_in[4];
    const float* bih0 = (const float*)d_in[5];
    const float* bhh0 = (const float*)d_in[6];
    const float* Wih1 = (const float*)d_in[7];
    const float* Whh1 = (const float*)d_in[8];
    const float* bih1 = (const float*)d_in[9];
    const float* bhh1 = (const float*)d_in[10];
    float* out = (float*)d_out;

    lstm2_kernel<<<B / 2, 64>>>(x, h0, c0, Wih0, Whh0, bih0, bhh0,
                                Wih1, Whh1, bih1, bhh1, out);
}

// round 11
// speedup vs baseline: 1.8472x; 1.0270x over previous
#include <cuda_runtime.h>

// ---------------------------------------------------------------------------
// 2-layer LSTM, B=2048, T=2048, I=1, H=16.
// R9 (resubmit after infra failure) = R8 + paired memory ops:
//   - one LDG.64 x-load per superstep PAIR (no clamp needed in pairs)
//   - one coalesced STG.32 per PAIR: half0 stores h1(s), half1 stores h1(s+1)
//     at outbase + s*16 + lane (contiguous 128B across the warp)
// FMA accumulator structure byte-identical to R8 (8 live u64 accums).
// ---------------------------------------------------------------------------

static constexpr int B = 2048;
static constexpr int T = 2048;
static constexpr int H = 16;

static __device__ __forceinline__ unsigned long long fma2(unsigned long long a,
                                                          unsigned long long b,
                                                          unsigned long long c) {
    unsigned long long d;
    asm("fma.rn.f32x2 %0, %1, %2, %3;" : "=l"(d) : "l"(a), "l"(b), "l"(c));
    return d;
}
static __device__ __forceinline__ unsigned long long pk2(float a, float b) {
    unsigned long long r;
    asm("mov.b64 %0, {%1, %2};" : "=l"(r) : "f"(a), "f"(b));
    return r;
}
static __device__ __forceinline__ void unpk2(unsigned long long v, float& a, float& b) {
    asm("mov.b64 {%0, %1}, %2;" : "=f"(a), "=f"(b) : "l"(v));
}
static __device__ __forceinline__ float tanhA(float x) {
    float r; asm("tanh.approx.f32 %0, %1;" : "=f"(r) : "f"(x)); return r;
}

__global__ __launch_bounds__(64, 7)
void lstm2_kernel(const float* __restrict__ x,
                  const float* __restrict__ h0in,
                  const float* __restrict__ c0in,
                  const float* __restrict__ Wih0,
                  const float* __restrict__ Whh0,
                  const float* __restrict__ bih0,
                  const float* __restrict__ bhh0,
                  const float* __restrict__ Wih1,
                  const float* __restrict__ Whh1,
                  const float* __restrict__ bih1,
                  const float* __restrict__ bhh1,
                  float* __restrict__ out)
{
    __shared__ __align__(16) float smh[2][2][32];

    const int tid  = threadIdx.x;
    const int wid  = tid >> 5;
    const int lane = tid & 31;
    const int j    = lane & 15;
    const int half = lane >> 4;
    const int b    = blockIdx.x * 2 + wid;

    const int gA = half * 32 + j;
    const int gB = gA + 16;

    const float scA = half ? 1.0f : 0.5f;
    const float scB = 0.5f;

    unsigned long long w0A[8], w0B[8], wiA[8], wiB[8], w1A[8], w1B[8];
    const float2* Wh0v = reinterpret_cast<const float2*>(Whh0);
    const float2* Wi1v = reinterpret_cast<const float2*>(Wih1);
    const float2* Wh1v = reinterpret_cast<const float2*>(Whh1);
#pragma unroll
    for (int p = 0; p < 8; ++p) {
        float2 a  = Wh0v[gA * 8 + p]; w0A[p] = pk2(a.x * scA, a.y * scA);
        float2 b2 = Wh0v[gB * 8 + p]; w0B[p] = pk2(b2.x * scB, b2.y * scB);
        float2 c  = Wi1v[gA * 8 + p]; wiA[p] = pk2(c.x * scA, c.y * scA);
        float2 d  = Wi1v[gB * 8 + p]; wiB[p] = pk2(d.x * scB, d.y * scB);
        float2 e  = Wh1v[gA * 8 + p]; w1A[p] = pk2(e.x * scA, e.y * scA);
        float2 f  = Wh1v[gB * 8 + p]; w1B[p] = pk2(f.x * scB, f.y * scB);
    }
    const unsigned long long bias2A0 = pk2((bih0[gA] + bhh0[gA]) * scA, 0.0f);
    const unsigned long long bias2B0 = pk2((bih0[gB] + bhh0[gB]) * scB, 0.0f);
    const unsigned long long bias2A1 = pk2((bih1[gA] + bhh1[gA]) * scA, 0.0f);
    const unsigned long long bias2B1 = pk2((bih1[gB] + bhh1[gB]) * scB, 0.0f);
    const float wxA = Wih0[gA] * scA;
    const float wxB = Wih0[gB] * scB;
    const unsigned long long ONE2 = pk2(1.0f, 1.0f);

    const float mA = half ? 1.0f : 0.5f;
    const float cA = half ? 0.0f : 0.5f;

    float c0v = c0in[b * H + j];
    float c1v = c0in[B * H + b * H + j];
    float h0v = h0in[b * H + j];
    float h1v = h0in[B * H + b * H + j];

    float* bufA = smh[wid][0];
    float* bufB = smh[wid][1];
    bufA[j + half * 16] = half ? h1v : h0v;
    __syncwarp();

    const float* xrow = x + (size_t)b * T;
    float*       outq = out + (size_t)b * T * H + lane;

    {
        const float xv0 = __ldg(xrow);
        const ulonglong2* hp = reinterpret_cast<const ulonglong2*>(bufA);
        ulonglong2 u0 = hp[0], u1 = hp[1], u2 = hp[2], u3 = hp[3];
        unsigned long long aA = bias2A0, aB = bias2B0, aA2 = 0ull, aB2 = 0ull;
        aA  = fma2(w0A[0], u0.x, aA);   aB  = fma2(w0B[0], u0.x, aB);
        aA  = fma2(w0A[1], u0.y, aA);   aB  = fma2(w0B[1], u0.y, aB);
        aA  = fma2(w0A[2], u1.x, aA);   aB  = fma2(w0B[2], u1.x, aB);
        aA  = fma2(w0A[3], u1.y, aA);   aB  = fma2(w0B[3], u1.y, aB);
        aA2 = fma2(w0A[4], u2.x, aA2);  aB2 = fma2(w0B[4], u2.x, aB2);
        aA2 = fma2(w0A[5], u2.y, aA2);  aB2 = fma2(w0B[5], u2.y, aB2);
        aA2 = fma2(w0A[6], u3.x, aA2);  aB2 = fma2(w0B[6], u3.x, aB2);
        aA2 = fma2(w0A[7], u3.y, aA2);  aB2 = fma2(w0B[7], u3.y, aB2);
        aA  = fma2(aA2, ONE2, aA);      aB  = fma2(aB2, ONE2, aB);
        float aL, aH, bL, bH;
        unpk2(aA, aL, aH); unpk2(aB, bL, bH);
        const float gAraw = fmaf(xv0, wxA, aL + aH);
        const float gBraw = fmaf(xv0, wxB, bL + bH);
        const float sA = fmaf(mA, tanhA(gAraw), cA);
        const float sB = fmaf(0.5f, tanhA(gBraw), 0.5f);
        const float gg = __shfl_xor_sync(0xffffffffu, sA, 16);
        const float oo = __shfl_xor_sync(0xffffffffu, sB, 16);
        const float f_eff = half ? oo : sB;
        const float o_eff = half ? sB : oo;
        c0v = fmaf(f_eff, c0v, sA * gg);
        h0v = o_eff * tanhA(c0v);
        __syncwarp();
        if (!half) bufA[j] = h0v;
        __syncwarp();
    }

    float xv = __ldg(xrow + 1);

#define SSCORE(RB, WB)                                                         \
    {                                                                          \
        const ulonglong2* hp0 = reinterpret_cast<const ulonglong2*>(RB);       \
        const ulonglong2* hp1 = reinterpret_cast<const ulonglong2*>((RB) + 16);\
        ulonglong2 u0 = hp0[0], u1 = hp0[1], u2 = hp0[2], u3 = hp0[3];         \
        ulonglong2 v0 = hp1[0], v1 = hp1[1], v2 = hp1[2], v3 = hp1[3];         \
        unsigned long long pA = bias2A0, pB = bias2B0, pA2 = 0ull, pB2 = 0ull; \
        pA  = fma2(w0A[0], u0.x, pA);   pB  = fma2(w0B[0], u0.x, pB);          \
        pA  = fma2(w0A[1], u0.y, pA);   pB  = fma2(w0B[1], u0.y, pB);          \
        pA  = fma2(w0A[2], u1.x, pA);   pB  = fma2(w0B[2], u1.x, pB);          \
        pA  = fma2(w0A[3], u1.y, pA);   pB  = fma2(w0B[3], u1.y, pB);          \
        pA2 = fma2(w0A[4], u2.x, pA2);  pB2 = fma2(w0B[4], u2.x, pB2);         \
        pA2 = fma2(w0A[5], u2.y, pA2);  pB2 = fma2(w0B[5], u2.y, pB2);         \
        pA2 = fma2(w0A[6], u3.x, pA2);  pB2 = fma2(w0B[6], u3.x, pB2);         \
        pA2 = fma2(w0A[7], u3.y, pA2);  pB2 = fma2(w0B[7], u3.y, pB2);         \
        unsigned long long qUA = bias2A1, qUB = bias2B1;                       \
        unsigned long long qVA = 0ull,   qVB = 0ull;                           \
        qUA = fma2(wiA[0], u0.x, qUA);  qUB = fma2(wiB[0], u0.x, qUB);         \
        qVA = fma2(w1A[0], v0.x, qVA);  qVB = fma2(w1B[0], v0.x, qVB);         \
        qUA = fma2(wiA[1], u0.y, qUA);  qUB = fma2(wiB[1], u0.y, qUB);         \
        qVA = fma2(w1A[1], v0.y, qVA);  qVB = fma2(w1B[1], v0.y, qVB);         \
        qUA = fma2(wiA[2], u1.x, qUA);  qUB = fma2(wiB[2], u1.x, qUB);         \
        qVA = fma2(w1A[2], v1.x, qVA);  qVB = fma2(w1B[2], v1.x, qVB);         \
        qUA = fma2(wiA[3], u1.y, qUA);  qUB = fma2(wiB[3], u1.y, qUB);         \
        qVA = fma2(w1A[3], v1.y, qVA);  qVB = fma2(w1B[3], v1.y, qVB);         \
        qUA = fma2(wiA[4], u2.x, qUA);  qUB = fma2(wiB[4], u2.x, qUB);         \
        qVA = fma2(w1A[4], v2.x, qVA);  qVB = fma2(w1B[4], v2.x, qVB);         \
        qUA = fma2(wiA[5], u2.y, qUA);  qUB = fma2(wiB[5], u2.y, qUB);         \
        qVA = fma2(w1A[5], v2.y, qVA);  qVB = fma2(w1B[5], v2.y, qVB);         \
        qUA = fma2(wiA[6], u3.x, qUA);  qUB = fma2(wiB[6], u3.x, qUB);         \
        qVA = fma2(w1A[6], v3.x, qVA);  qVB = fma2(w1B[6], v3.x, qVB);         \
        qUA = fma2(wiA[7], u3.y, qUA);  qUB = fma2(wiB[7], u3.y, qUB);         \
        qVA = fma2(w1A[7], v3.y, qVA);  qVB = fma2(w1B[7], v3.y, qVB);         \
        const unsigned long long paA = fma2(pA2, ONE2, pA);                    \
        const unsigned long long paB = fma2(pB2, ONE2, pB);                    \
        const unsigned long long qaA = fma2(qVA, ONE2, qUA);                   \
        const unsigned long long qaB = fma2(qVB, ONE2, qUB);                   \
        float paL, paH, pbL, pbH, qaL, qaH, qbL, qbH;                          \
        unpk2(paA, paL, paH); unpk2(paB, pbL, pbH);                            \
        unpk2(qaA, qaL, qaH); unpk2(qaB, qbL, qbH);                            \
        const float pAraw = fmaf(xv, wxA, paL + paH);                          \
        const float pBraw = fmaf(xv, wxB, pbL + pbH);                          \
        const float qAraw = qaL + qaH;                                         \
        const float qBraw = qbL + qbH;                                         \
        const float psA = fmaf(mA, tanhA(pAraw), cA);                          \
        const float qsA = fmaf(mA, tanhA(qAraw), cA);                          \
        const float psB = fmaf(0.5f, tanhA(pBraw), 0.5f);                      \
        const float qsB = fmaf(0.5f, tanhA(qBraw), 0.5f);                      \
        const float pgg = __shfl_xor_sync(0xffffffffu, psA, 16);               \
        const float qgg = __shfl_xor_sync(0xffffffffu, qsA, 16);               \
        const float poo = __shfl_xor_sync(0xffffffffu, psB, 16);               \
        const float qoo = __shfl_xor_sync(0xffffffffu, qsB, 16);               \
        const float pf = half ? poo : psB;                                     \
        const float po = half ? psB : poo;                                     \
        const float qf = half ? qoo : qsB;                                     \
        const float qo = half ? qsB : qoo;                                     \
        c0v = fmaf(pf, c0v, psA * pgg);                                        \
        c1v = fmaf(qf, c1v, qsA * qgg);                                        \
        h0v = po * tanhA(c0v);                                                 \
        h1v = qo * tanhA(c1v);                                                 \
        (WB)[j + half * 16] = half ? h1v : h0v;                                \
        __syncwarp();                                                          \
    }

    for (int s = 0; s < T - 3; s += 2) {
        const float2 xn2 = *reinterpret_cast<const float2*>(xrow + s + 2);
        SSCORE(bufA, bufB)
        const float h1A = h1v;
        xv = xn2.x;
        SSCORE(bufB, bufA)
        outq[s * H] = half ? h1v : h1A;   // out[b,s,j] / out[b,s+1,j]
        xv = xn2.y;
    }

    // single superstep s = T-2 (xv = x[T-1]); half0 lanes store out[b,T-2,j]
    {
        SSCORE(bufA, bufB)
        if (!half) outq[(T - 2) * H] = h1v;
    }

    // tail: layer1 step T-1 (reads bufB); half0 lanes store out[b,T-1,j]
    {
        const ulonglong2* hp0 = reinterpret_cast<const ulonglong2*>(bufB);
        const ulonglong2* hp1 = reinterpret_cast<const ulonglong2*>(bufB + 16);
        ulonglong2 u0 = hp0[0], u1 = hp0[1], u2 = hp0[2], u3 = hp0[3];
        ulonglong2 v0 = hp1[0], v1 = hp1[1], v2 = hp1[2], v3 = hp1[3];
        unsigned long long qUA = bias2A1, qUB = bias2B1;
        unsigned long long qVA = 0ull,   qVB = 0ull;
        qUA = fma2(wiA[0], u0.x, qUA);  qUB = fma2(wiB[0], u0.x, qUB);
        qVA = fma2(w1A[0], v0.x, qVA);  qVB = fma2(w1B[0], v0.x, qVB);
        qUA = fma2(wiA[1], u0.y, qUA);  qUB = fma2(wiB[1], u0.y, qUB);
        qVA = fma2(w1A[1], v0.y, qVA);  qVB = fma2(w1B[1], v0.y, qVB);
        qUA = fma2(wiA[2], u1.x, qUA);  qUB = fma2(wiB[2], u1.x, qUB);
        qVA = fma2(w1A[2], v1.x, qVA);  qVB = fma2(w1B[2], v1.x, qVB);
        qUA = fma2(wiA[3], u1.y, qUA);  qUB = fma2(wiB[3], u1.y, qUB);
        qVA = fma2(w1A[3], v1.y, qVA);  qVB = fma2(w1B[3], v1.y, qVB);
        qUA = fma2(wiA[4], u2.x, qUA);  qUB = fma2(wiB[4], u2.x, qUB);
        qVA = fma2(w1A[4], v2.x, qVA);  qVB = fma2(w1B[4], v2.x, qVB);
        qUA = fma2(wiA[5], u2.y, qUA);  qUB = fma2(wiB[5], u2.y, qUB);
        qVA = fma2(w1A[5], v2.y, qVA);  qVB = fma2(w1B[5], v2.y, qVB);
        qUA = fma2(wiA[6], u3.x, qUA);  qUB = fma2(wiB[6], u3.x, qUB);
        qVA = fma2(w1A[6], v3.x, qVA);  qVB = fma2(w1B[6], v3.x, qVB);
        qUA = fma2(wiA[7], u3.y, qUA);  qUB = fma2(wiB[7], u3.y, qUB);
        qVA = fma2(w1A[7], v3.y, qVA);  qVB = fma2(w1B[7], v3.y, qVB);
        const unsigned long long qaA = fma2(qVA, ONE2, qUA);
        const unsigned long long qaB = fma2(qVB, ONE2, qUB);
        float qaL, qaH, qbL, qbH;
        unpk2(qaA, qaL, qaH); unpk2(qaB, qbL, qbH);
        const float qAraw = qaL + qaH;
        const float qBraw = qbL + qbH;
        const float qsA = fmaf(mA, tanhA(qAraw), cA);
        const float qsB = fmaf(0.5f, tanhA(qBraw), 0.5f);
        const float qgg = __shfl_xor_sync(0xffffffffu, qsA, 16);
        const float qoo = __shfl_xor_sync(0xffffffffu, qsB, 16);
        const float qf = half ? qoo : qsB;
        const float qo = half ? qsB : qoo;
        c1v = fmaf(qf, c1v, qsA * qgg);
        h1v = qo * tanhA(c1v);
        if (!half) outq[(T - 1) * H] = h1v;
    }

    {
        float* hN = out + (size_t)B * T * H;
        float* cN = hN + 2 * B * H;
        const int off = half * (B * H) + b * H + j;
        hN[off] = half ? h1v : h0v;
        cN[off] = half ? c1v : c0v;
    }
}

extern "C" void kernel_launch(void* const* d_in, const int* in_sizes, int n_in,
                              void* d_out, int out_size) {
    const float* x    = (const float*)d_in[0];
    const float* h0   = (const float*)d_in[1];
    const float* c0   = (const float*)d_in[2];
    const float* Wih0 = (const float*)d_in[3];
    const float* Whh0 = (const float*)d_in[4];
    const float* bih0 = (const float*)d_in[5];
    const float* bhh0 = (const float*)d_in[6];
    const float* Wih1 = (const float*)d_in[7];
    const float* Whh1 = (const float*)d_in[8];
    const float* bih1 = (const float*)d_in[9];
    const float* bhh1 = (const float*)d_in[10];
    float* out = (float*)d_out;

    lstm2_kernel<<<B / 2, 64>>>(x, h0, c0, Wih0, Whh0, bih0, bhh0,
                                Wih1, Whh1, bih1, bhh1, out);
}

// round 12
// speedup vs baseline: 1.8659x; 1.0101x over previous
#include <cuda_runtime.h>

// ---------------------------------------------------------------------------
// 2-layer LSTM, B=2048, T=2048, I=1, H=16.
// R12 = R11 (paired LDG.64 x-loads, paired coalesced STG, prescaled sigmoid
// rows, branch-free epilogue, 8-accumulator FFMA2 block) with the in-loop
// __syncwarp() replaced by a zero-cost compiler memory fence: the loop body
// is fully convergent, so same-warp in-order MIO guarantees STS->LDS
// visibility across lanes; the fence only blocks compiler reordering.
// Also: running output pointer (strength reduction).
// ---------------------------------------------------------------------------

static constexpr int B = 2048;
static constexpr int T = 2048;
static constexpr int H = 16;

#define WFENCE() asm volatile("" ::: "memory")

static __device__ __forceinline__ unsigned long long fma2(unsigned long long a,
                                                          unsigned long long b,
                                                          unsigned long long c) {
    unsigned long long d;
    asm("fma.rn.f32x2 %0, %1, %2, %3;" : "=l"(d) : "l"(a), "l"(b), "l"(c));
    return d;
}
static __device__ __forceinline__ unsigned long long pk2(float a, float b) {
    unsigned long long r;
    asm("mov.b64 %0, {%1, %2};" : "=l"(r) : "f"(a), "f"(b));
    return r;
}
static __device__ __forceinline__ void unpk2(unsigned long long v, float& a, float& b) {
    asm("mov.b64 {%0, %1}, %2;" : "=f"(a), "=f"(b) : "l"(v));
}
static __device__ __forceinline__ float tanhA(float x) {
    float r; asm("tanh.approx.f32 %0, %1;" : "=f"(r) : "f"(x)); return r;
}

__global__ __launch_bounds__(64, 7)
void lstm2_kernel(const float* __restrict__ x,
                  const float* __restrict__ h0in,
                  const float* __restrict__ c0in,
                  const float* __restrict__ Wih0,
                  const float* __restrict__ Whh0,
                  const float* __restrict__ bih0,
                  const float* __restrict__ bhh0,
                  const float* __restrict__ Wih1,
                  const float* __restrict__ Whh1,
                  const float* __restrict__ bih1,
                  const float* __restrict__ bhh1,
                  float* __restrict__ out)
{
    __shared__ __align__(16) float smh[2][2][32];

    const int tid  = threadIdx.x;
    const int wid  = tid >> 5;
    const int lane = tid & 31;
    const int j    = lane & 15;
    const int half = lane >> 4;
    const int b    = blockIdx.x * 2 + wid;

    const int gA = half * 32 + j;
    const int gB = gA + 16;

    const float scA = half ? 1.0f : 0.5f;
    const float scB = 0.5f;

    unsigned long long w0A[8], w0B[8], wiA[8], wiB[8], w1A[8], w1B[8];
    const float2* Wh0v = reinterpret_cast<const float2*>(Whh0);
    const float2* Wi1v = reinterpret_cast<const float2*>(Wih1);
    const float2* Wh1v = reinterpret_cast<const float2*>(Whh1);
#pragma unroll
    for (int p = 0; p < 8; ++p) {
        float2 a  = Wh0v[gA * 8 + p]; w0A[p] = pk2(a.x * scA, a.y * scA);
        float2 b2 = Wh0v[gB * 8 + p]; w0B[p] = pk2(b2.x * scB, b2.y * scB);
        float2 c  = Wi1v[gA * 8 + p]; wiA[p] = pk2(c.x * scA, c.y * scA);
        float2 d  = Wi1v[gB * 8 + p]; wiB[p] = pk2(d.x * scB, d.y * scB);
        float2 e  = Wh1v[gA * 8 + p]; w1A[p] = pk2(e.x * scA, e.y * scA);
        float2 f  = Wh1v[gB * 8 + p]; w1B[p] = pk2(f.x * scB, f.y * scB);
    }
    const unsigned long long bias2A0 = pk2((bih0[gA] + bhh0[gA]) * scA, 0.0f);
    const unsigned long long bias2B0 = pk2((bih0[gB] + bhh0[gB]) * scB, 0.0f);
    const unsigned long long bias2A1 = pk2((bih1[gA] + bhh1[gA]) * scA, 0.0f);
    const unsigned long long bias2B1 = pk2((bih1[gB] + bhh1[gB]) * scB, 0.0f);
    const float wxA = Wih0[gA] * scA;
    const float wxB = Wih0[gB] * scB;
    const unsigned long long ONE2 = pk2(1.0f, 1.0f);

    const float mA = half ? 1.0f : 0.5f;
    const float cA = half ? 0.0f : 0.5f;

    float c0v = c0in[b * H + j];
    float c1v = c0in[B * H + b * H + j];
    float h0v = h0in[b * H + j];
    float h1v = h0in[B * H + b * H + j];

    float* bufA = smh[wid][0];
    float* bufB = smh[wid][1];
    bufA[j + half * 16] = half ? h1v : h0v;
    __syncwarp();

    const float* xrow = x + (size_t)b * T;
    float*       outq = out + (size_t)b * T * H + lane;

    {
        const float xv0 = __ldg(xrow);
        const ulonglong2* hp = reinterpret_cast<const ulonglong2*>(bufA);
        ulonglong2 u0 = hp[0], u1 = hp[1], u2 = hp[2], u3 = hp[3];
        unsigned long long aA = bias2A0, aB = bias2B0, aA2 = 0ull, aB2 = 0ull;
        aA  = fma2(w0A[0], u0.x, aA);   aB  = fma2(w0B[0], u0.x, aB);
        aA  = fma2(w0A[1], u0.y, aA);   aB  = fma2(w0B[1], u0.y, aB);
        aA  = fma2(w0A[2], u1.x, aA);   aB  = fma2(w0B[2], u1.x, aB);
        aA  = fma2(w0A[3], u1.y, aA);   aB  = fma2(w0B[3], u1.y, aB);
        aA2 = fma2(w0A[4], u2.x, aA2);  aB2 = fma2(w0B[4], u2.x, aB2);
        aA2 = fma2(w0A[5], u2.y, aA2);  aB2 = fma2(w0B[5], u2.y, aB2);
        aA2 = fma2(w0A[6], u3.x, aA2);  aB2 = fma2(w0B[6], u3.x, aB2);
        aA2 = fma2(w0A[7], u3.y, aA2);  aB2 = fma2(w0B[7], u3.y, aB2);
        aA  = fma2(aA2, ONE2, aA);      aB  = fma2(aB2, ONE2, aB);
        float aL, aH, bL, bH;
        unpk2(aA, aL, aH); unpk2(aB, bL, bH);
        const float gAraw = fmaf(xv0, wxA, aL + aH);
        const float gBraw = fmaf(xv0, wxB, bL + bH);
        const float sA = fmaf(mA, tanhA(gAraw), cA);
        const float sB = fmaf(0.5f, tanhA(gBraw), 0.5f);
        const float gg = __shfl_xor_sync(0xffffffffu, sA, 16);
        const float oo = __shfl_xor_sync(0xffffffffu, sB, 16);
        const float f_eff = half ? oo : sB;
        const float o_eff = half ? sB : oo;
        c0v = fmaf(f_eff, c0v, sA * gg);
        h0v = o_eff * tanhA(c0v);
        __syncwarp();
        if (!half) bufA[j] = h0v;
        __syncwarp();
    }

    float xv = __ldg(xrow + 1);

#define SSCORE(RB, WB)                                                         \
    {                                                                          \
        const ulonglong2* hp0 = reinterpret_cast<const ulonglong2*>(RB);       \
        const ulonglong2* hp1 = reinterpret_cast<const ulonglong2*>((RB) + 16);\
        ulonglong2 u0 = hp0[0], u1 = hp0[1], u2 = hp0[2], u3 = hp0[3];         \
        ulonglong2 v0 = hp1[0], v1 = hp1[1], v2 = hp1[2], v3 = hp1[3];         \
        unsigned long long pA = bias2A0, pB = bias2B0, pA2 = 0ull, pB2 = 0ull; \
        pA  = fma2(w0A[0], u0.x, pA);   pB  = fma2(w0B[0], u0.x, pB);          \
        pA  = fma2(w0A[1], u0.y, pA);   pB  = fma2(w0B[1], u0.y, pB);          \
        pA  = fma2(w0A[2], u1.x, pA);   pB  = fma2(w0B[2], u1.x, pB);          \
        pA  = fma2(w0A[3], u1.y, pA);   pB  = fma2(w0B[3], u1.y, pB);          \
        pA2 = fma2(w0A[4], u2.x, pA2);  pB2 = fma2(w0B[4], u2.x, pB2);         \
        pA2 = fma2(w0A[5], u2.y, pA2);  pB2 = fma2(w0B[5], u2.y, pB2);         \
        pA2 = fma2(w0A[6], u3.x, pA2);  pB2 = fma2(w0B[6], u3.x, pB2);         \
        pA2 = fma2(w0A[7], u3.y, pA2);  pB2 = fma2(w0B[7], u3.y, pB2);         \
        unsigned long long qUA = bias2A1, qUB = bias2B1;                       \
        unsigned long long qVA = 0ull,   qVB = 0ull;                           \
        qUA = fma2(wiA[0], u0.x, qUA);  qUB = fma2(wiB[0], u0.x, qUB);         \
        qVA = fma2(w1A[0], v0.x, qVA);  qVB = fma2(w1B[0], v0.x, qVB);         \
        qUA = fma2(wiA[1], u0.y, qUA);  qUB = fma2(wiB[1], u0.y, qUB);         \
        qVA = fma2(w1A[1], v0.y, qVA);  qVB = fma2(w1B[1], v0.y, qVB);         \
        qUA = fma2(wiA[2], u1.x, qUA);  qUB = fma2(wiB[2], u1.x, qUB);         \
        qVA = fma2(w1A[2], v1.x, qVA);  qVB = fma2(w1B[2], v1.x, qVB);         \
        qUA = fma2(wiA[3], u1.y, qUA);  qUB = fma2(wiB[3], u1.y, qUB);         \
        qVA = fma2(w1A[3], v1.y, qVA);  qVB = fma2(w1B[3], v1.y, qVB);         \
        qUA = fma2(wiA[4], u2.x, qUA);  qUB = fma2(wiB[4], u2.x, qUB);         \
        qVA = fma2(w1A[4], v2.x, qVA);  qVB = fma2(w1B[4], v2.x, qVB);         \
        qUA = fma2(wiA[5], u2.y, qUA);  qUB = fma2(wiB[5], u2.y, qUB);         \
        qVA = fma2(w1A[5], v2.y, qVA);  qVB = fma2(w1B[5], v2.y, qVB);         \
        qUA = fma2(wiA[6], u3.x, qUA);  qUB = fma2(wiB[6], u3.x, qUB);         \
        qVA = fma2(w1A[6], v3.x, qVA);  qVB = fma2(w1B[6], v3.x, qVB);         \
        qUA = fma2(wiA[7], u3.y, qUA);  qUB = fma2(wiB[7], u3.y, qUB);         \
        qVA = fma2(w1A[7], v3.y, qVA);  qVB = fma2(w1B[7], v3.y, qVB);         \
        const unsigned long long paA = fma2(pA2, ONE2, pA);                    \
        const unsigned long long paB = fma2(pB2, ONE2, pB);                    \
        const unsigned long long qaA = fma2(qVA, ONE2, qUA);                   \
        const unsigned long long qaB = fma2(qVB, ONE2, qUB);                   \
        float paL, paH, pbL, pbH, qaL, qaH, qbL, qbH;                          \
        unpk2(paA, paL, paH); unpk2(paB, pbL, pbH);                            \
        unpk2(qaA, qaL, qaH); unpk2(qaB, qbL, qbH);                            \
        const float pAraw = fmaf(xv, wxA, paL + paH);                          \
        const float pBraw = fmaf(xv, wxB, pbL + pbH);                          \
        const float qAraw = qaL + qaH;                                         \
        const float qBraw = qbL + qbH;                                         \
        const float psA = fmaf(mA, tanhA(pAraw), cA);                          \
        const float qsA = fmaf(mA, tanhA(qAraw), cA);                          \
        const float psB = fmaf(0.5f, tanhA(pBraw), 0.5f);                      \
        const float qsB = fmaf(0.5f, tanhA(qBraw), 0.5f);                      \
        const float pgg = __shfl_xor_sync(0xffffffffu, psA, 16);               \
        const float qgg = __shfl_xor_sync(0xffffffffu, qsA, 16);               \
        const float poo = __shfl_xor_sync(0xffffffffu, psB, 16);               \
        const float qoo = __shfl_xor_sync(0xffffffffu, qsB, 16);               \
        const float pf = half ? poo : psB;                                     \
        const float po = half ? psB : poo;                                     \
        const float qf = half ? qoo : qsB;                                     \
        const float qo = half ? qsB : qoo;                                     \
        c0v = fmaf(pf, c0v, psA * pgg);                                        \
        c1v = fmaf(qf, c1v, qsA * qgg);                                        \
        h0v = po * tanhA(c0v);                                                 \
        h1v = qo * tanhA(c1v);                                                 \
        (WB)[j + half * 16] = half ? h1v : h0v;                                \
        WFENCE();                                                              \
    }

    {
        float* op = outq;
        for (int s = 0; s < T - 3; s += 2) {
            const float2 xn2 = *reinterpret_cast<const float2*>(xrow + s + 2);
            SSCORE(bufA, bufB)
            const float h1A = h1v;
            xv = xn2.x;
            SSCORE(bufB, bufA)
            *op = half ? h1v : h1A;       // out[b,s,j] / out[b,s+1,j]
            op += 2 * H;
            xv = xn2.y;
        }
    }

    // single superstep s = T-2 (xv = x[T-1]); half0 lanes store out[b,T-2,j]
    {
        SSCORE(bufA, bufB)
        if (!half) outq[(T - 2) * H] = h1v;
    }

    // tail: layer1 step T-1 (reads bufB); half0 lanes store out[b,T-1,j]
    {
        const ulonglong2* hp0 = reinterpret_cast<const ulonglong2*>(bufB);
        const ulonglong2* hp1 = reinterpret_cast<const ulonglong2*>(bufB + 16);
        ulonglong2 u0 = hp0[0], u1 = hp0[1], u2 = hp0[2], u3 = hp0[3];
        ulonglong2 v0 = hp1[0], v1 = hp1[1], v2 = hp1[2], v3 = hp1[3];
        unsigned long long qUA = bias2A1, qUB = bias2B1;
        unsigned long long qVA = 0ull,   qVB = 0ull;
        qUA = fma2(wiA[0], u0.x, qUA);  qUB = fma2(wiB[0], u0.x, qUB);
        qVA = fma2(w1A[0], v0.x, qVA);  qVB = fma2(w1B[0], v0.x, qVB);
        qUA = fma2(wiA[1], u0.y, qUA);  qUB = fma2(wiB[1], u0.y, qUB);
        qVA = fma2(w1A[1], v0.y, qVA);  qVB = fma2(w1B[1], v0.y, qVB);
        qUA = fma2(wiA[2], u1.x, qUA);  qUB = fma2(wiB[2], u1.x, qUB);
        qVA = fma2(w1A[2], v1.x, qVA);  qVB = fma2(w1B[2], v1.x, qVB);
        qUA = fma2(wiA[3], u1.y, qUA);  qUB = fma2(wiB[3], u1.y, qUB);
        qVA = fma2(w1A[3], v1.y, qVA);  qVB = fma2(w1B[3], v1.y, qVB);
        qUA = fma2(wiA[4], u2.x, qUA);  qUB = fma2(wiB[4], u2.x, qUB);
        qVA = fma2(w1A[4], v2.x, qVA);  qVB = fma2(w1B[4], v2.x, qVB);
        qUA = fma2(wiA[5], u2.y, qUA);  qUB = fma2(wiB[5], u2.y, qUB);
        qVA = fma2(w1A[5], v2.y, qVA);  qVB = fma2(w1B[5], v2.y, qVB);
        qUA = fma2(wiA[6], u3.x, qUA);  qUB = fma2(wiB[6], u3.x, qUB);
        qVA = fma2(w1A[6], v3.x, qVA);  qVB = fma2(w1B[6], v3.x, qVB);
        qUA = fma2(wiA[7], u3.y, qUA);  qUB = fma2(wiB[7], u3.y, qUB);
        qVA = fma2(w1A[7], v3.y, qVA);  qVB = fma2(w1B[7], v3.y, qVB);
        const unsigned long long qaA = fma2(qVA, ONE2, qUA);
        const unsigned long long qaB = fma2(qVB, ONE2, qUB);
        float qaL, qaH, qbL, qbH;
        unpk2(qaA, qaL, qaH); unpk2(qaB, qbL, qbH);
        const float qAraw = qaL + qaH;
        const float qBraw = qbL + qbH;
        const float qsA = fmaf(mA, tanhA(qAraw), cA);
        const float qsB = fmaf(0.5f, tanhA(qBraw), 0.5f);
        const float qgg = __shfl_xor_sync(0xffffffffu, qsA, 16);
        const float qoo = __shfl_xor_sync(0xffffffffu, qsB, 16);
        const float qf = half ? qoo : qsB;
        const float qo = half ? qsB : qoo;
        c1v = fmaf(qf, c1v, qsA * qgg);
        h1v = qo * tanhA(c1v);
        if (!half) outq[(T - 1) * H] = h1v;
    }

    {
        float* hN = out + (size_t)B * T * H;
        float* cN = hN + 2 * B * H;
        const int off = half * (B * H) + b * H + j;
        hN[off] = half ? h1v : h0v;
        cN[off] = half ? c1v : c0v;
    }
}

extern "C" void kernel_launch(void* const* d_in, const int* in_sizes, int n_in,
                              void* d_out, int out_size) {
    const float* x    = (const float*)d_in[0];
    const float* h0   = (const float*)d_in[1];
    const float* c0   = (const float*)d_in[2];
    const float* Wih0 = (const float*)d_in[3];
    const float* Whh0 = (const float*)d_in[4];
    const float* bih0 = (const float*)d_in[5];
    const float* bhh0 = (const float*)d_in[6];
    const float* Wih1 = (const float*)d_in[7];
    const float* Whh1 = (const float*)d_in[8];
    const float* bih1 = (const float*)d_in[9];
    const float* bhh1 = (const float*)d_in[10];
    float* out = (float*)d_out;

    lstm2_kernel<<<B / 2, 64>>>(x, h0, c0, Wih0, Whh0, bih0, bhh0,
                                Wih1, Whh1, bih1, bhh1, out);
}